// round 11
// baseline (speedup 1.0000x reference)
#include <cuda_runtime.h>
#include <cuda_fp16.h>
#include <math.h>
#include <stdint.h>

// ============================================================================
// Problem constants
// ============================================================================
#define B_   4
#define S_   2048
#define IN_  512
#define H_   1024
#define M_   (B_ * S_)   // 8192
#define AW   33          // 2*atten_size + 1

// ============================================================================
// Device global scratch (allocation-free per harness rules)
// ============================================================================
__device__ __half g_xhi[(size_t)M_ * IN_];
__device__ __half g_hhi[(size_t)M_ * H_];
__device__ __half g_qhi[(size_t)M_ * H_];
__device__ __half g_w1t_hi[(size_t)H_ * IN_];   // W1^T [1024,512]
__device__ __half g_wqt_hi[(size_t)H_ * H_];    // Wq^T [1024,1024]

// ============================================================================
// PTX helpers (base sm_103 ISA only: cp.async, ldmatrix, mma.sync)
// ============================================================================
__device__ __forceinline__ uint32_t smem_u32(const void* p) {
    uint32_t a;
    asm("{ .reg .u64 t; cvta.to.shared.u64 t, %1; cvt.u32.u64 %0, t; }"
        : "=r"(a) : "l"(p));
    return a;
}

__device__ __forceinline__ void cp_async16(uint32_t dst, const void* src) {
    asm volatile("cp.async.cg.shared.global [%0], [%1], 16;"
                 :: "r"(dst), "l"(src));
}
#define CP_COMMIT() asm volatile("cp.async.commit_group;" ::: "memory")
#define CP_WAIT(n)  asm volatile("cp.async.wait_group %0;" :: "n"(n) : "memory")

__device__ __forceinline__ void ldsm_x4(uint32_t* r, uint32_t addr) {
    asm volatile("ldmatrix.sync.aligned.m8n8.x4.shared.b16 {%0,%1,%2,%3}, [%4];"
                 : "=r"(r[0]), "=r"(r[1]), "=r"(r[2]), "=r"(r[3]) : "r"(addr));
}

__device__ __forceinline__ void mma_f16(float* c, const uint32_t* a,
                                        uint32_t b0, uint32_t b1) {
    asm volatile(
        "mma.sync.aligned.m16n8k16.row.col.f32.f16.f16.f32 "
        "{%0,%1,%2,%3}, {%4,%5,%6,%7}, {%8,%9}, {%0,%1,%2,%3};"
        : "+f"(c[0]), "+f"(c[1]), "+f"(c[2]), "+f"(c[3])
        : "r"(a[0]), "r"(a[1]), "r"(a[2]), "r"(a[3]), "r"(b0), "r"(b1));
}

// unpack 8 halves (uint4) -> 8 floats
__device__ __forceinline__ void h8_to_f8(uint4 v, float* f) {
    union { uint32_t u; __half2 h; } c;
    c.u = v.x; float2 t0 = __half22float2(c.h);
    c.u = v.y; float2 t1 = __half22float2(c.h);
    c.u = v.z; float2 t2 = __half22float2(c.h);
    c.u = v.w; float2 t3 = __half22float2(c.h);
    f[0] = t0.x; f[1] = t0.y; f[2] = t1.x; f[3] = t1.y;
    f[4] = t2.x; f[5] = t2.y; f[6] = t3.x; f[7] = t3.y;
}

// ============================================================================
// Convert kernels
// ============================================================================
__global__ void split_hi_kernel(const float* __restrict__ in,
                                __half* __restrict__ hi, int n4) {
    int i = blockIdx.x * blockDim.x + threadIdx.x;
    if (i >= n4) return;
    float4 v = ((const float4*)in)[i];
    ((__half2*)hi)[i * 2 + 0] = __halves2half2(__float2half_rn(v.x),
                                               __float2half_rn(v.y));
    ((__half2*)hi)[i * 2 + 1] = __halves2half2(__float2half_rn(v.z),
                                               __float2half_rn(v.w));
}

// in [R, C] fp32 -> out^T [C, R] half
__global__ void transpose_hi_kernel(const float* __restrict__ in,
                                    __half* __restrict__ hiT,
                                    int R, int C) {
    __shared__ float t[32][33];
    const int c0 = blockIdx.x * 32, r0 = blockIdx.y * 32;
    const int tx = threadIdx.x, ty = threadIdx.y;   // 32 x 8
    #pragma unroll
    for (int j = 0; j < 32; j += 8)
        t[ty + j][tx] = in[(size_t)(r0 + ty + j) * C + c0 + tx];
    __syncthreads();
    #pragma unroll
    for (int j = 0; j < 32; j += 8) {
        hiT[(size_t)(c0 + ty + j) * R + r0 + tx] = __float2half_rn(t[tx][ty + j]);
    }
}

// ============================================================================
// HMMA GEMM (1-term fp16): C[M,N] = A[M,K] @ W[K,N], W transposed [N,K].
// Block tile 128x128, BK=64/stage, 8 warps (warp tile 32x64), NST=3,
// 96KB smem -> 2 CTAs/SM.  SMEM row (128B): [k0..31 | k32..63],
// 16B groups XOR (row&7).  Output fp16 (optionally bias+relu).
// ============================================================================
#define NST 3
#define A_BYTES 16384                    // 128 rows x 128B
#define STAGE_BYTES (A_BYTES + 16384)    // + B: 128 rows x 128B
#define GEMM_SMEM (NST * STAGE_BYTES)    // 96 KB

template <bool RELU_BIAS>
__global__ __launch_bounds__(256, 2)
void hmma_gemm(const __half* __restrict__ Ahi,
               const __half* __restrict__ Bhi,
               const float* __restrict__ bias,
               __half* __restrict__ outHi,
               int K)
{
    extern __shared__ __align__(1024) char smem[];
    const uint32_t smBase = smem_u32(smem);

    const int tid  = threadIdx.x;
    const int wid  = tid >> 5;
    const int lane = tid & 31;
    const int m0 = blockIdx.y * 128;
    const int n0 = blockIdx.x * 128;
    const int nk = K / 64;                    // BK=64 per stage

    const int wm = (wid & 3) * 32;            // 4 warps over m
    const int wn = (wid >> 2) * 64;           // 2 warps over n

    // --- loader: each thread loads half (k0/k32) of one A row + one B row ---
    const int half_sel = tid & 1;
    const int row = tid >> 1;                 // 0..127
    const __half* srcA = Ahi + (size_t)(m0 + row) * K + half_sel * 32;
    const __half* srcB = Bhi + (size_t)(n0 + row) * K + half_sel * 32;
    uint32_t dstA[4], dstB[4];
    #pragma unroll
    for (int g = 0; g < 4; g++) {
        const int lg = half_sel * 4 + g;
        const int pg = (lg ^ (row & 7)) * 16;
        dstA[g] = smBase + row * 128 + pg;
        dstB[g] = smBase + A_BYTES + row * 128 + pg;
    }

    auto load_stage = [&](int c, int s) {
        const uint32_t so = s * STAGE_BYTES;
        const __half* sa = srcA + c * 64;
        const __half* sb = srcB + c * 64;
        #pragma unroll
        for (int g = 0; g < 4; g++) {
            cp_async16(dstA[g] + so, sa + g * 8);
            cp_async16(dstB[g] + so, sb + g * 8);
        }
    };

    float acc[2][8][4];
    #pragma unroll
    for (int mt = 0; mt < 2; mt++)
        #pragma unroll
        for (int nt = 0; nt < 8; nt++)
            #pragma unroll
            for (int j = 0; j < 4; j++)
                acc[mt][nt][j] = 0.f;

    #pragma unroll
    for (int c = 0; c < NST - 1; c++) {
        load_stage(c, c);
        CP_COMMIT();
    }

    const int arow_l = (lane & 15);
    const int agrp_l = (lane >> 4);
    const int brow_l = (lane & 7) + ((lane >> 4) << 3);
    const int bgrp_l = (lane >> 3) & 1;

    for (int c = 0; c < nk; c++) {
        CP_WAIT(NST - 2);
        __syncthreads();
        if (c + NST - 1 < nk)
            load_stage(c + NST - 1, (c + NST - 1) % NST);
        CP_COMMIT();

        const uint32_t aB = smBase + (c % NST) * STAGE_BYTES;
        const uint32_t bB = aB + A_BYTES;

        #pragma unroll
        for (int ks = 0; ks < 4; ks++) {           // 4 k-steps of 16
            const int agH = ks * 2 + agrp_l;       // groups 0..7
            const int bgH = ks * 2 + bgrp_l;

            uint32_t bf[4][4];
            #pragma unroll
            for (int np = 0; np < 4; np++) {
                const int r = wn + np * 16 + brow_l;
                ldsm_x4(bf[np], bB + r * 128 + ((bgH ^ (r & 7)) * 16));
            }

            #pragma unroll
            for (int mt = 0; mt < 2; mt++) {
                const int r = wm + mt * 16 + arow_l;
                uint32_t af[4];
                ldsm_x4(af, aB + r * 128 + ((agH ^ (r & 7)) * 16));
                #pragma unroll
                for (int nt = 0; nt < 8; nt++) {
                    const int np = nt >> 1, o = (nt & 1) * 2;
                    mma_f16(acc[mt][nt], af, bf[np][o], bf[np][o + 1]);
                }
            }
        }
    }

    // ---------------- epilogue: fp16 only ----------------
    const int r0 = lane >> 2;
    const int c0 = (lane & 3) * 2;

    #pragma unroll
    for (int mt = 0; mt < 2; mt++) {
        #pragma unroll
        for (int h = 0; h < 2; h++) {
            const int row_o = m0 + wm + mt * 16 + h * 8 + r0;
            __half* op = outHi + (size_t)row_o * H_ + n0 + wn + c0;
            #pragma unroll
            for (int nt = 0; nt < 8; nt++) {
                float vx = acc[mt][nt][h * 2 + 0];
                float vy = acc[mt][nt][h * 2 + 1];
                if (RELU_BIAS) {
                    const int gc = n0 + wn + nt * 8 + c0;
                    vx = fmaxf(vx + bias[gc], 0.f);
                    vy = fmaxf(vy + bias[gc + 1], 0.f);
                }
                *(__half2*)(op + nt * 8) =
                    __halves2half2(__float2half_rn(vx), __float2half_rn(vy));
            }
        }
    }
}

// ============================================================================
// Local windowed attention — fp16 resident neighborhood (unchanged)
// ============================================================================
#define TS 16
#define HPH 1032   // row pitch in halves (2064 B)
#define ATT_SMEM (48 * HPH * 2 + TS * 36 * 4)

__global__ __launch_bounds__(256, 2)
void atten_kernel(const __half* __restrict__ hh, const __half* __restrict__ qh,
                  float* __restrict__ out)
{
    extern __shared__ __align__(16) char asmem[];
    __half* hs = (__half*)asmem;                       // [48][HPH]
    float (*sc)[36] = (float(*)[36])(asmem + 48 * HPH * 2);

    const int tid = threadIdx.x;
    const int b = blockIdx.y;
    const int s0 = blockIdx.x * TS;

    const __half* hB = hh + (size_t)b * S_ * H_;
    const __half* qB = qh + (size_t)b * S_ * H_;
    float*        oB = out + (size_t)b * S_ * H_;

    // ---- load 48 x 1024 fp16 neighborhood once ----
    for (int i = tid; i < 48 * 128; i += 256) {
        const int r = i >> 7;
        const int c = (i & 127) * 8;
        const int g = s0 - 16 + r;
        uint4 v = make_uint4(0, 0, 0, 0);
        if (g >= 0 && g < S_)
            v = *(const uint4*)(hB + (size_t)g * H_ + c);
        *(uint4*)&hs[r * HPH + c] = v;
    }
    __syncthreads();

    // ---------------- Phase A: scores ----------------
    const int warp = tid >> 5, lane = tid & 31;
    const int lane16 = lane & 15;
    const int sA = warp * 2 + (lane >> 4);   // 0..15
    const int kofs = lane16 * 8;

    float acc[AW];
    #pragma unroll
    for (int w = 0; w < AW; w++) acc[w] = 0.f;

    for (int kc = 0; kc < H_; kc += 128) {
        float qv[8];
        h8_to_f8(*(const uint4*)(qB + (size_t)(s0 + sA) * H_ + kc + kofs), qv);

        #pragma unroll
        for (int w = 0; w < AW; w++) {
            float hv[8];
            h8_to_f8(*(const uint4*)&hs[(sA + 32 - w) * HPH + kc + kofs], hv);
            float s = acc[w];
            #pragma unroll
            for (int k = 0; k < 8; k++) s += qv[k] * hv[k];
            acc[w] = s;
        }
    }

    #pragma unroll
    for (int w = 0; w < AW; w++) {
        #pragma unroll
        for (int d = 8; d >= 1; d >>= 1)
            acc[w] += __shfl_xor_sync(0xffffffffu, acc[w], d);
    }
    #pragma unroll
    for (int w = 0; w < AW; w++) {
        if ((w & 15) == lane16 && (w < 32 || lane16 == 0))
            sc[sA][w] = acc[w] * 0.03125f;   // 1/sqrt(1024)
    }
    __syncthreads();

    // ---------------- Phase B: softmax ----------------
    if (tid < TS) {
        float m = -1e30f;
        for (int w = 0; w < AW; w++) m = fmaxf(m, sc[tid][w]);
        float sum = 0.f;
        for (int w = 0; w < AW; w++) {
            const float e = expf(sc[tid][w] - m);
            sc[tid][w] = e;
            sum += e;
        }
        const float inv = 1.f / sum;
        for (int w = 0; w < AW; w++) sc[tid][w] *= inv;
    }
    __syncthreads();

    // ---------------- Phase C: weighted sum ----------------
    const int sg = ((tid >> 4) & 7) * 2;
    const int cg = (tid & 15) * 8;
    const int hsel = tid >> 7;

    for (int ci = 0; ci < 4; ci++) {
        const int kc = (hsel * 4 + ci) * 128;
        float a0[8], a1[8];
        #pragma unroll
        for (int k = 0; k < 8; k++) { a0[k] = 0.f; a1[k] = 0.f; }

        #pragma unroll
        for (int j = 0; j < 34; j++) {
            float hv[8];
            h8_to_f8(*(const uint4*)&hs[(sg + j) * HPH + kc + cg], hv);
            if (j <= 32) {
                const float p = sc[sg][32 - j];
                #pragma unroll
                for (int k = 0; k < 8; k++) a0[k] += p * hv[k];
            }
            if (j >= 1) {
                const float p = sc[sg + 1][33 - j];
                #pragma unroll
                for (int k = 0; k < 8; k++) a1[k] += p * hv[k];
            }
        }
        float* o0 = oB + (size_t)(s0 + sg) * H_ + kc + cg;
        float* o1 = oB + (size_t)(s0 + sg + 1) * H_ + kc + cg;
        *(float4*)(o0)     = make_float4(a0[0], a0[1], a0[2], a0[3]);
        *(float4*)(o0 + 4) = make_float4(a0[4], a0[5], a0[6], a0[7]);
        *(float4*)(o1)     = make_float4(a1[0], a1[1], a1[2], a1[3]);
        *(float4*)(o1 + 4) = make_float4(a1[4], a1[5], a1[6], a1[7]);
    }
}

// ============================================================================
// Launch
// ============================================================================
extern "C" void kernel_launch(void* const* d_in, const int* in_sizes, int n_in,
                              void* d_out, int out_size)
{
    const float* x  = (const float*)d_in[0];   // [4,2048,512]
    const float* W1 = (const float*)d_in[1];   // [512,1024]
    const float* b1 = (const float*)d_in[2];   // [1024]
    const float* Wq = (const float*)d_in[3];   // [1024,1024]
    float* out = (float*)d_out;                // [4,2048,1024]

    __half *xhi, *hhi, *qhi, *w1thi, *wqthi;
    cudaGetSymbolAddress((void**)&xhi, g_xhi);
    cudaGetSymbolAddress((void**)&hhi, g_hhi);
    cudaGetSymbolAddress((void**)&qhi, g_qhi);
    cudaGetSymbolAddress((void**)&w1thi, g_w1t_hi);
    cudaGetSymbolAddress((void**)&wqthi, g_wqt_hi);

    cudaFuncSetAttribute((const void*)hmma_gemm<true>,
                         cudaFuncAttributeMaxDynamicSharedMemorySize, GEMM_SMEM);
    cudaFuncSetAttribute((const void*)hmma_gemm<false>,
                         cudaFuncAttributeMaxDynamicSharedMemorySize, GEMM_SMEM);
    cudaFuncSetAttribute((const void*)atten_kernel,
                         cudaFuncAttributeMaxDynamicSharedMemorySize, ATT_SMEM);

    // Converts
    {
        int n4 = M_ * IN_ / 4;
        split_hi_kernel<<<(n4 + 255) / 256, 256>>>(x, xhi, n4);
        dim3 t(32, 8);
        transpose_hi_kernel<<<dim3(H_ / 32, IN_ / 32), t>>>(W1, w1thi, IN_, H_);
        transpose_hi_kernel<<<dim3(H_ / 32, H_ / 32), t>>>(Wq, wqthi, H_, H_);
    }

    // GEMM1: hhi = fp16(relu(xhi @ W1hi + b1))
    {
        dim3 grid(H_ / 128, M_ / 128);
        hmma_gemm<true><<<grid, 256, GEMM_SMEM>>>(xhi, w1thi, b1, hhi, IN_);
    }
    // GEMM2: qhi = fp16(hhi @ Wqhi)
    {
        dim3 grid(H_ / 128, M_ / 128);
        hmma_gemm<false><<<grid, 256, GEMM_SMEM>>>(hhi, wqthi, nullptr, qhi, H_);
    }
    // Attention
    {
        dim3 grid(S_ / TS, B_);
        atten_kernel<<<grid, 256, ATT_SMEM>>>(hhi, qhi, out);
    }
}